// round 16
// baseline (speedup 1.0000x reference)
#include <cuda_runtime.h>
#include <cuda_bf16.h>
#include <cstdint>

#define Nn 50000
#define Ee 800000
#define ET (Ee + Nn)       // edges + self loops
#define F_IN 16
#define Hh 8
#define HID 128
#define NEG_SLOPE 0.2f

// ---------------- scratch (no allocations allowed) ----------------
// g_deg is zero-initialized at module load and re-zeroed by k_scan_c every
// call (after k_scan_a consumes it), so no clear kernel is needed.
__device__ float    g_h0[Nn * HID];     // gemm output h
__device__ float    g_h1[Nn * HID];     // layer output (elu)
__device__ float    g_alS[Nn * Hh];
__device__ float    g_alD[Nn * Hh];
__device__ unsigned g_maxS[3 * Hh];     // per-layer per-head global max of alS
__device__ int      g_deg[Nn];
__device__ int      g_rowptr[Nn + 1];
__device__ int      g_cursor[Nn];
__device__ int      g_csrsrc[ET];
__device__ int      g_bsum[128];

// monotone float<->uint key for atomicMax on floats
__device__ __forceinline__ unsigned fkeyu(float f) {
    unsigned b = __float_as_uint(f);
    return (b & 0x80000000u) ? ~b : (b | 0x80000000u);
}
__device__ __forceinline__ float fkeyinv(unsigned k) {
    unsigned b = (k & 0x80000000u) ? (k & 0x7fffffffu) : ~k;
    return __uint_as_float(b);
}
// tf32 round: destination of cvt.rna.tf32.f32 is a b32 register
__device__ __forceinline__ float tf32r(float f) {
    uint32_t r;
    asm("cvt.rna.tf32.f32 %0, %1;" : "=r"(r) : "f"(f));
    return __uint_as_float(r);
}
__device__ __forceinline__ void mma_tf32(float* c, const float* a, const float* b) {
    asm volatile(
        "mma.sync.aligned.m16n8k8.row.col.f32.tf32.tf32.f32 "
        "{%0,%1,%2,%3}, {%4,%5,%6,%7}, {%8,%9}, {%0,%1,%2,%3};\n"
        : "+f"(c[0]), "+f"(c[1]), "+f"(c[2]), "+f"(c[3])
        : "r"(__float_as_uint(a[0])), "r"(__float_as_uint(a[1])),
          "r"(__float_as_uint(a[2])), "r"(__float_as_uint(a[3])),
          "r"(__float_as_uint(b[0])), "r"(__float_as_uint(b[1])));
}

// ---------------- CSR build ----------------
__global__ void k_hist(const int* __restrict__ ei) {
    int e = blockIdx.x * blockDim.x + threadIdx.x;
    if (e >= ET) return;
    int d = (e < Ee) ? ei[Ee + e] : (e - Ee);
    atomicAdd(&g_deg[d], 1);
}

#define SB 512
#define NB ((Nn + SB - 1) / SB)   // 98

__global__ void k_scan_a() {
    __shared__ int sm[SB];
    int b = blockIdx.x, t = threadIdx.x;
    int i = b * SB + t;
    int v = (i < Nn) ? g_deg[i] : 0;
    sm[t] = v;
    __syncthreads();
    for (int o = 1; o < SB; o <<= 1) {
        int u = (t >= o) ? sm[t - o] : 0;
        __syncthreads();
        sm[t] += u;
        __syncthreads();
    }
    if (i < Nn) g_rowptr[i] = sm[t] - v;   // block-local exclusive
    if (t == SB - 1) g_bsum[b] = sm[t];    // block total
}

// scan_c: cross-block prefix (reduce g_bsum[0..b-1]) + re-zero g_deg for the
// next call + init all three layers' g_maxS slots (runs before any GEMM).
__global__ void k_scan_c() {
    __shared__ int s_off[4];
    int b = blockIdx.x, t = threadIdx.x;

    int v = (t < NB && t < b) ? g_bsum[t] : 0;   // NB=98 < 128
    if (t < 128) {
#pragma unroll
        for (int o = 16; o; o >>= 1) v += __shfl_xor_sync(0xffffffffu, v, o);
        if ((t & 31) == 0) s_off[t >> 5] = v;
    }
    __syncthreads();
    int off = s_off[0] + s_off[1] + s_off[2] + s_off[3];

    int i = b * SB + t;
    if (i < Nn) {
        int r = g_rowptr[i] + off;
        g_rowptr[i] = r;
        g_cursor[i] = r;
        g_deg[i] = 0;                       // restore for next call's k_hist
    }
    if (b == 0 && t == 0) g_rowptr[Nn] = ET;
    if (b == 0 && t < 3 * Hh) g_maxS[t] = fkeyu(-1e30f);
}

__global__ void k_scatter(const int* __restrict__ ei) {
    int e = blockIdx.x * blockDim.x + threadIdx.x;
    if (e >= ET) return;
    int d, s;
    if (e < Ee) { s = ei[e]; d = ei[Ee + e]; }
    else        { s = e - Ee; d = e - Ee; }
    int pos = atomicAdd(&g_cursor[d], 1);
    g_csrsrc[pos] = s;
}

// ---------------- layer-1 GEMM (F_IN=16, SIMT fp32) + logits ----------------
__global__ __launch_bounds__(128) void gemm_al_kernel(
    const float* __restrict__ x, const float* __restrict__ W,
    const float* __restrict__ aS, const float* __restrict__ aD)
{
    constexpr int KT = 16;
    __shared__ float Ws[KT][HID];
    __shared__ float xs[KT][32];
    __shared__ unsigned s_mx[Hh];
    float* __restrict__ hout = g_h0;

    int tid = threadIdx.x;
    int cx = tid & 31, ry = tid >> 5;
    int r0 = blockIdx.x * 32;
    float acc[8][4] = {};

    if (tid < Hh) s_mx[tid] = fkeyu(-1e30f);

    for (int kt = 0; kt < F_IN; kt += KT) {
#pragma unroll
        for (int k = 0; k < KT; k++) Ws[k][tid] = W[(kt + k) * HID + tid];
#pragma unroll
        for (int it = 0; it < 4; it++) {
            int lin = tid + it * 128;
            int r = lin >> 4, k = lin & 15;
            int row = r0 + r;
            xs[k][r] = (row < Nn) ? x[row * F_IN + kt + k] : 0.f;
        }
        __syncthreads();
#pragma unroll
        for (int k = 0; k < KT; k++) {
            float4 w4 = *(const float4*)&Ws[k][cx * 4];
#pragma unroll
            for (int r = 0; r < 8; r++) {
                float xv = xs[k][ry * 8 + r];
                acc[r][0] += xv * w4.x;
                acc[r][1] += xv * w4.y;
                acc[r][2] += xv * w4.z;
                acc[r][3] += xv * w4.w;
            }
        }
        __syncthreads();
    }

    int hd = cx >> 2;
    float a_s[4], a_d[4];
#pragma unroll
    for (int j = 0; j < 4; j++) {
        int c = (cx * 4 + j) & 15;
        a_s[j] = aS[hd * 16 + c];
        a_d[j] = aD[hd * 16 + c];
    }
    float locmax = -1e30f;
#pragma unroll
    for (int r = 0; r < 8; r++) {
        int row = r0 + ry * 8 + r;
        if (row >= Nn) break;
        float4 hv = make_float4(acc[r][0], acc[r][1], acc[r][2], acc[r][3]);
        *(float4*)&hout[row * HID + cx * 4] = hv;
        float ps = acc[r][0] * a_s[0] + acc[r][1] * a_s[1] + acc[r][2] * a_s[2] + acc[r][3] * a_s[3];
        float pd = acc[r][0] * a_d[0] + acc[r][1] * a_d[1] + acc[r][2] * a_d[2] + acc[r][3] * a_d[3];
        ps += __shfl_xor_sync(0xffffffffu, ps, 1);
        ps += __shfl_xor_sync(0xffffffffu, ps, 2);
        pd += __shfl_xor_sync(0xffffffffu, pd, 1);
        pd += __shfl_xor_sync(0xffffffffu, pd, 2);
        if ((cx & 3) == 0) {
            g_alS[row * Hh + hd] = ps;
            g_alD[row * Hh + hd] = pd;
            locmax = fmaxf(locmax, ps);
        }
    }
    if ((cx & 3) == 0) atomicMax(&s_mx[hd], fkeyu(locmax));
    __syncthreads();
    if (tid < Hh) atomicMax(&g_maxS[tid], s_mx[tid]);   // layer 0 slots
}

// ---------------- layers 2/3 GEMM (128x128, tf32 tensor cores) + logits ------
#define WS_STR 136
#define XS_STR 132
#define NTILES ((Nn + 63) / 64)   // 782
#define SMEM_TF (128 * WS_STR * 4 + 64 * XS_STR * 4 + 32)

__global__ __launch_bounds__(256, 2) void gemm_tf32_kernel(
    const float* __restrict__ W,
    const float* __restrict__ aS, const float* __restrict__ aD,
    int mslot)
{
    extern __shared__ float smem[];
    float* Ws = smem;                          // [128][WS_STR]
    float* xs = smem + 128 * WS_STR;           // [64][XS_STR]
    unsigned* s_mx = (unsigned*)(xs + 64 * XS_STR);

    int tid = threadIdx.x;
    int warp = tid >> 5, lane = tid & 31;
    int mw = warp >> 2, nw = warp & 3;
    int g = lane >> 2, t = lane & 3;

    for (int i = tid; i < 128 * 128; i += 256) {
        int k = i >> 7, n = i & 127;
        Ws[k * WS_STR + n] = tf32r(W[i]);
    }
    if (tid < Hh) s_mx[tid] = fkeyu(-1e30f);

    float asv0[4], asv1[4], adv0[4], adv1[4];
#pragma unroll
    for (int nt = 0; nt < 4; nt++) {
        int col = nw * 32 + nt * 8 + 2 * t;
        asv0[nt] = aS[col]; asv1[nt] = aS[col + 1];
        adv0[nt] = aD[col]; adv1[nt] = aD[col + 1];
    }
    __syncthreads();

    for (int tile = blockIdx.x; tile < NTILES; tile += gridDim.x) {
        int row0 = tile * 64;

        for (int i = tid; i < 64 * 32; i += 256) {
            int r = i >> 5, c4 = i & 31;
            int row = row0 + r;
            float4 v = make_float4(0.f, 0.f, 0.f, 0.f);
            if (row < Nn) v = *(const float4*)&g_h1[row * HID + c4 * 4];
            float* p = &xs[r * XS_STR + c4 * 4];
            p[0] = tf32r(v.x); p[1] = tf32r(v.y); p[2] = tf32r(v.z); p[3] = tf32r(v.w);
        }
        __syncthreads();

        float c[2][4][4];
#pragma unroll
        for (int mt = 0; mt < 2; mt++)
#pragma unroll
            for (int nt = 0; nt < 4; nt++)
#pragma unroll
                for (int q = 0; q < 4; q++) c[mt][nt][q] = 0.f;

#pragma unroll
        for (int ks = 0; ks < 16; ks++) {
            int k0 = ks * 8;
            float a[2][4], b[4][2];
#pragma unroll
            for (int mt = 0; mt < 2; mt++) {
                int r = mw * 32 + mt * 16 + g;
                a[mt][0] = xs[r * XS_STR + k0 + t];
                a[mt][1] = xs[(r + 8) * XS_STR + k0 + t];
                a[mt][2] = xs[r * XS_STR + k0 + t + 4];
                a[mt][3] = xs[(r + 8) * XS_STR + k0 + t + 4];
            }
#pragma unroll
            for (int nt = 0; nt < 4; nt++) {
                int n = nw * 32 + nt * 8 + g;
                b[nt][0] = Ws[(k0 + t) * WS_STR + n];
                b[nt][1] = Ws[(k0 + t + 4) * WS_STR + n];
            }
#pragma unroll
            for (int mt = 0; mt < 2; mt++)
#pragma unroll
                for (int nt = 0; nt < 4; nt++)
                    mma_tf32(c[mt][nt], a[mt], b[nt]);
        }

        float ps[2][2][2] = {}, pd[2][2][2] = {};   // [mt][half][headidx]
#pragma unroll
        for (int mt = 0; mt < 2; mt++) {
            int rlo = row0 + mw * 32 + mt * 16 + g;
            int rhi = rlo + 8;
#pragma unroll
            for (int nt = 0; nt < 4; nt++) {
                int col = nw * 32 + nt * 8 + 2 * t;
                float c0 = c[mt][nt][0], c1 = c[mt][nt][1];
                float c2 = c[mt][nt][2], c3 = c[mt][nt][3];
                if (rlo < Nn) { float2 v = make_float2(c0, c1); *(float2*)&g_h0[rlo * HID + col] = v; }
                if (rhi < Nn) { float2 v = make_float2(c2, c3); *(float2*)&g_h0[rhi * HID + col] = v; }
                int hi = nt >> 1;
                ps[mt][0][hi] += c0 * asv0[nt] + c1 * asv1[nt];
                ps[mt][1][hi] += c2 * asv0[nt] + c3 * asv1[nt];
                pd[mt][0][hi] += c0 * adv0[nt] + c1 * adv1[nt];
                pd[mt][1][hi] += c2 * adv0[nt] + c3 * adv1[nt];
            }
        }
#pragma unroll
        for (int mt = 0; mt < 2; mt++)
#pragma unroll
            for (int hf = 0; hf < 2; hf++)
#pragma unroll
                for (int hi = 0; hi < 2; hi++) {
                    float v = ps[mt][hf][hi];
                    v += __shfl_xor_sync(0xffffffffu, v, 1);
                    v += __shfl_xor_sync(0xffffffffu, v, 2);
                    ps[mt][hf][hi] = v;
                    float w = pd[mt][hf][hi];
                    w += __shfl_xor_sync(0xffffffffu, w, 1);
                    w += __shfl_xor_sync(0xffffffffu, w, 2);
                    pd[mt][hf][hi] = w;
                }
        if (t == 0) {
            float lm0 = -1e30f, lm1 = -1e30f;
#pragma unroll
            for (int mt = 0; mt < 2; mt++)
#pragma unroll
                for (int hf = 0; hf < 2; hf++) {
                    int row = row0 + mw * 32 + mt * 16 + hf * 8 + g;
                    if (row < Nn) {
                        int head = nw * 2;
                        g_alS[row * Hh + head]     = ps[mt][hf][0];
                        g_alD[row * Hh + head]     = pd[mt][hf][0];
                        g_alS[row * Hh + head + 1] = ps[mt][hf][1];
                        g_alD[row * Hh + head + 1] = pd[mt][hf][1];
                        lm0 = fmaxf(lm0, ps[mt][hf][0]);
                        lm1 = fmaxf(lm1, ps[mt][hf][1]);
                    }
                }
            atomicMax(&s_mx[nw * 2],     fkeyu(lm0));
            atomicMax(&s_mx[nw * 2 + 1], fkeyu(lm1));
        }
        __syncthreads();
    }
    if (tid < Hh) atomicMax(&g_maxS[mslot + tid], s_mx[tid]);
}

// ---------------- fused edge kernel (R9 form): softmax + aggregate + elu -----
// One warp per dst node, 8 warps/block; lane owns channels [4*lane,4*lane+4).
// Unroll-4 gather + software-pipelined src-index chunk loads. mslot selects
// the layer's maxS slots.
template <bool FC>
__global__ __launch_bounds__(256) void agg2_kernel(
    const float* __restrict__ bias,
    const float* __restrict__ fcw, const float* __restrict__ fcb,
    float* __restrict__ fco, int mslot)
{
    int warp = threadIdx.x >> 5, lane = threadIdx.x & 31;
    int d = blockIdx.x * 8 + warp;
    if (d >= Nn) return;
    int hd = lane >> 2;

    float alDh = g_alD[d * Hh + hd];
    float cb = fkeyinv(g_maxS[mslot + hd]) + alDh;
    cb = (cb > 0.f) ? cb : NEG_SLOPE * cb;

    int beg = g_rowptr[d], end = g_rowptr[d + 1];
    float4 acc = make_float4(0.f, 0.f, 0.f, 0.f);
    float den = 0.f;

    int cnt = min(32, end - beg);
    int s32 = (lane < cnt) ? g_csrsrc[beg + lane] : 0;

    for (int base = beg; base < end; ) {
        int nbase = base + 32;
        int ncnt = min(32, end - nbase);
        int ns32 = (nbase < end && lane < ncnt) ? g_csrsrc[nbase + lane] : 0;

        int jj = 0;
        for (; jj + 4 <= cnt; jj += 4) {
            int s0 = __shfl_sync(0xffffffffu, s32, jj);
            int s1 = __shfl_sync(0xffffffffu, s32, jj + 1);
            int s2 = __shfl_sync(0xffffffffu, s32, jj + 2);
            int s3 = __shfl_sync(0xffffffffu, s32, jj + 3);
            float l0 = g_alS[s0 * Hh + hd] + alDh;
            float l1 = g_alS[s1 * Hh + hd] + alDh;
            float l2 = g_alS[s2 * Hh + hd] + alDh;
            float l3 = g_alS[s3 * Hh + hd] + alDh;
            float4 h0 = *(const float4*)&g_h0[s0 * HID + lane * 4];
            float4 h1 = *(const float4*)&g_h0[s1 * HID + lane * 4];
            float4 h2 = *(const float4*)&g_h0[s2 * HID + lane * 4];
            float4 h3 = *(const float4*)&g_h0[s3 * HID + lane * 4];
            l0 = (l0 > 0.f) ? l0 : NEG_SLOPE * l0;
            l1 = (l1 > 0.f) ? l1 : NEG_SLOPE * l1;
            l2 = (l2 > 0.f) ? l2 : NEG_SLOPE * l2;
            l3 = (l3 > 0.f) ? l3 : NEG_SLOPE * l3;
            float p0 = __expf(l0 - cb);
            float p1 = __expf(l1 - cb);
            float p2 = __expf(l2 - cb);
            float p3 = __expf(l3 - cb);
            acc.x += p0 * h0.x + p1 * h1.x + p2 * h2.x + p3 * h3.x;
            acc.y += p0 * h0.y + p1 * h1.y + p2 * h2.y + p3 * h3.y;
            acc.z += p0 * h0.z + p1 * h1.z + p2 * h2.z + p3 * h3.z;
            acc.w += p0 * h0.w + p1 * h1.w + p2 * h2.w + p3 * h3.w;
            den += (p0 + p1) + (p2 + p3);
        }
        for (; jj < cnt; jj++) {
            int s0 = __shfl_sync(0xffffffffu, s32, jj);
            float l0 = g_alS[s0 * Hh + hd] + alDh;
            l0 = (l0 > 0.f) ? l0 : NEG_SLOPE * l0;
            float p0 = __expf(l0 - cb);
            float4 h0 = *(const float4*)&g_h0[s0 * HID + lane * 4];
            acc.x += p0 * h0.x;
            acc.y += p0 * h0.y;
            acc.z += p0 * h0.z;
            acc.w += p0 * h0.w;
            den += p0;
        }

        base = nbase;
        cnt = ncnt;
        s32 = ns32;
    }

    float inv = 1.f / den;
    float4 b4 = *(const float4*)&bias[lane * 4];
    float4 o;
    o.x = acc.x * inv + b4.x;
    o.y = acc.y * inv + b4.y;
    o.z = acc.z * inv + b4.z;
    o.w = acc.w * inv + b4.w;
    o.x = (o.x > 0.f) ? o.x : (__expf(o.x) - 1.f);
    o.y = (o.y > 0.f) ? o.y : (__expf(o.y) - 1.f);
    o.z = (o.z > 0.f) ? o.z : (__expf(o.z) - 1.f);
    o.w = (o.w > 0.f) ? o.w : (__expf(o.w) - 1.f);

    if (!FC) {
        *(float4*)&g_h1[d * HID + lane * 4] = o;
    } else {
        float4 fw = *(const float4*)&fcw[lane * 4];
        float v = o.x * fw.x + o.y * fw.y + o.z * fw.z + o.w * fw.w;
#pragma unroll
        for (int off = 16; off; off >>= 1) v += __shfl_xor_sync(0xffffffffu, v, off);
        if (lane == 0) fco[d] = v + fcb[0];
    }
}

// ---------------- launch ----------------
extern "C" void kernel_launch(void* const* d_in, const int* in_sizes, int n_in,
                              void* d_out, int out_size)
{
    const float* x   = (const float*)d_in[0];
    const int*   ei  = (const int*)d_in[1];   // int32 (JAX default downcast)
    const float* W1  = (const float*)d_in[2];
    const float* a1s = (const float*)d_in[3];
    const float* a1d = (const float*)d_in[4];
    const float* b1  = (const float*)d_in[5];
    const float* W2  = (const float*)d_in[6];
    const float* a2s = (const float*)d_in[7];
    const float* a2d = (const float*)d_in[8];
    const float* b2  = (const float*)d_in[9];
    const float* W3  = (const float*)d_in[10];
    const float* a3s = (const float*)d_in[11];
    const float* a3d = (const float*)d_in[12];
    const float* b3  = (const float*)d_in[13];
    const float* fcw = (const float*)d_in[14];
    const float* fcb = (const float*)d_in[15];
    float* out = (float*)d_out;

    cudaFuncSetAttribute(gemm_tf32_kernel,
                         cudaFuncAttributeMaxDynamicSharedMemorySize, SMEM_TF);

    // CSR build: 4 kernels. g_deg is zero at module load; k_scan_c re-zeroes it
    // (and re-inits g_maxS) every call, so state is identical at each entry.
    k_hist<<<(ET + 255) / 256, 256>>>(ei);
    k_scan_a<<<NB, SB>>>();
    k_scan_c<<<NB, SB>>>();
    k_scatter<<<(ET + 255) / 256, 256>>>(ei);

    const int gemm1_blocks = (Nn + 31) / 32;
    const int agg_blocks   = (Nn + 7) / 8;

    // layer 1 (SIMT fp32, maxS slots 0..7)
    gemm_al_kernel<<<gemm1_blocks, 128>>>(x, W1, a1s, a1d);
    agg2_kernel<false><<<agg_blocks, 256>>>(b1, nullptr, nullptr, nullptr, 0);

    // layer 2 (tf32 tensor cores, maxS slots 8..15)
    gemm_tf32_kernel<<<296, 256, SMEM_TF>>>(W2, a2s, a2d, 8);
    agg2_kernel<false><<<agg_blocks, 256>>>(b2, nullptr, nullptr, nullptr, 8);

    // layer 3 (tf32 tensor cores, maxS slots 16..23, + fused fc head)
    gemm_tf32_kernel<<<296, 256, SMEM_TF>>>(W3, a3s, a3d, 16);
    agg2_kernel<true><<<agg_blocks, 256>>>(b3, fcw, fcb, out, 16);
}

// round 17
// speedup vs baseline: 1.0102x; 1.0102x over previous
#include <cuda_runtime.h>
#include <cuda_bf16.h>
#include <cstdint>

#define Nn 50000
#define Ee 800000
#define ET (Ee + Nn)       // edges + self loops
#define F_IN 16
#define Hh 8
#define HID 128
#define NEG_SLOPE 0.2f

// ---------------- scratch (no allocations allowed) ----------------
// g_deg is zero-initialized at module load and re-zeroed by k_scan_c every
// call (after k_scan_a consumes it), so no clear kernel is needed.
__device__ float    g_h0[Nn * HID];     // gemm output h
__device__ float    g_h1[Nn * HID];     // layer output (elu)
__device__ float    g_alS[Nn * Hh];
__device__ float    g_alD[Nn * Hh];
__device__ unsigned g_maxS[3 * Hh];     // per-layer per-head global max of alS
__device__ int      g_deg[Nn];
__device__ int      g_rowptr[Nn + 1];
__device__ int      g_cursor[Nn];
__device__ int      g_csrsrc[ET];
__device__ int      g_bsum[128];

// monotone float<->uint key for atomicMax on floats
__device__ __forceinline__ unsigned fkeyu(float f) {
    unsigned b = __float_as_uint(f);
    return (b & 0x80000000u) ? ~b : (b | 0x80000000u);
}
__device__ __forceinline__ float fkeyinv(unsigned k) {
    unsigned b = (k & 0x80000000u) ? (k & 0x7fffffffu) : ~k;
    return __uint_as_float(b);
}
// tf32 round: destination of cvt.rna.tf32.f32 is a b32 register
__device__ __forceinline__ float tf32r(float f) {
    uint32_t r;
    asm("cvt.rna.tf32.f32 %0, %1;" : "=r"(r) : "f"(f));
    return __uint_as_float(r);
}
__device__ __forceinline__ void mma_tf32(float* c, const float* a, const float* b) {
    asm volatile(
        "mma.sync.aligned.m16n8k8.row.col.f32.tf32.tf32.f32 "
        "{%0,%1,%2,%3}, {%4,%5,%6,%7}, {%8,%9}, {%0,%1,%2,%3};\n"
        : "+f"(c[0]), "+f"(c[1]), "+f"(c[2]), "+f"(c[3])
        : "r"(__float_as_uint(a[0])), "r"(__float_as_uint(a[1])),
          "r"(__float_as_uint(a[2])), "r"(__float_as_uint(a[3])),
          "r"(__float_as_uint(b[0])), "r"(__float_as_uint(b[1])));
}

// ---------------- CSR build ----------------
// 4 edges per thread: 4 independent atomics in flight (MLP=4 on the ATOMG
// chain) instead of 1 — attacks the atomic-latency bound seen in ncu.
__global__ void k_hist(const int* __restrict__ ei) {
    int e0 = (blockIdx.x * blockDim.x + threadIdx.x) * 4;
    if (e0 + 3 < ET) {
        int d0 = (e0     < Ee) ? ei[Ee + e0]     : (e0     - Ee);
        int d1 = (e0 + 1 < Ee) ? ei[Ee + e0 + 1] : (e0 + 1 - Ee);
        int d2 = (e0 + 2 < Ee) ? ei[Ee + e0 + 2] : (e0 + 2 - Ee);
        int d3 = (e0 + 3 < Ee) ? ei[Ee + e0 + 3] : (e0 + 3 - Ee);
        atomicAdd(&g_deg[d0], 1);
        atomicAdd(&g_deg[d1], 1);
        atomicAdd(&g_deg[d2], 1);
        atomicAdd(&g_deg[d3], 1);
    } else {
        for (int e = e0; e < ET; e++) {
            int d = (e < Ee) ? ei[Ee + e] : (e - Ee);
            atomicAdd(&g_deg[d], 1);
        }
    }
}

#define SB 512
#define NB ((Nn + SB - 1) / SB)   // 98

__global__ void k_scan_a() {
    __shared__ int sm[SB];
    int b = blockIdx.x, t = threadIdx.x;
    int i = b * SB + t;
    int v = (i < Nn) ? g_deg[i] : 0;
    sm[t] = v;
    __syncthreads();
    for (int o = 1; o < SB; o <<= 1) {
        int u = (t >= o) ? sm[t - o] : 0;
        __syncthreads();
        sm[t] += u;
        __syncthreads();
    }
    if (i < Nn) g_rowptr[i] = sm[t] - v;   // block-local exclusive
    if (t == SB - 1) g_bsum[b] = sm[t];    // block total
}

// scan_c: cross-block prefix (reduce g_bsum[0..b-1]) + re-zero g_deg for the
// next call + init all three layers' g_maxS slots (runs before any GEMM).
__global__ void k_scan_c() {
    __shared__ int s_off[4];
    int b = blockIdx.x, t = threadIdx.x;

    int v = (t < NB && t < b) ? g_bsum[t] : 0;   // NB=98 < 128
    if (t < 128) {
#pragma unroll
        for (int o = 16; o; o >>= 1) v += __shfl_xor_sync(0xffffffffu, v, o);
        if ((t & 31) == 0) s_off[t >> 5] = v;
    }
    __syncthreads();
    int off = s_off[0] + s_off[1] + s_off[2] + s_off[3];

    int i = b * SB + t;
    if (i < Nn) {
        int r = g_rowptr[i] + off;
        g_rowptr[i] = r;
        g_cursor[i] = r;
        g_deg[i] = 0;                       // restore for next call's k_hist
    }
    if (b == 0 && t == 0) g_rowptr[Nn] = ET;
    if (b == 0 && t < 3 * Hh) g_maxS[t] = fkeyu(-1e30f);
}

__global__ void k_scatter(const int* __restrict__ ei) {
    int e0 = (blockIdx.x * blockDim.x + threadIdx.x) * 4;
    if (e0 + 3 < ET) {
        int s0, d0, s1, d1, s2, d2, s3, d3;
        if (e0     < Ee) { s0 = ei[e0];     d0 = ei[Ee + e0];     } else { s0 = d0 = e0     - Ee; }
        if (e0 + 1 < Ee) { s1 = ei[e0 + 1]; d1 = ei[Ee + e0 + 1]; } else { s1 = d1 = e0 + 1 - Ee; }
        if (e0 + 2 < Ee) { s2 = ei[e0 + 2]; d2 = ei[Ee + e0 + 2]; } else { s2 = d2 = e0 + 2 - Ee; }
        if (e0 + 3 < Ee) { s3 = ei[e0 + 3]; d3 = ei[Ee + e0 + 3]; } else { s3 = d3 = e0 + 3 - Ee; }
        int p0 = atomicAdd(&g_cursor[d0], 1);
        int p1 = atomicAdd(&g_cursor[d1], 1);
        int p2 = atomicAdd(&g_cursor[d2], 1);
        int p3 = atomicAdd(&g_cursor[d3], 1);
        g_csrsrc[p0] = s0;
        g_csrsrc[p1] = s1;
        g_csrsrc[p2] = s2;
        g_csrsrc[p3] = s3;
    } else {
        for (int e = e0; e < ET; e++) {
            int s, d;
            if (e < Ee) { s = ei[e]; d = ei[Ee + e]; }
            else        { s = e - Ee; d = e - Ee; }
            int pos = atomicAdd(&g_cursor[d], 1);
            g_csrsrc[pos] = s;
        }
    }
}

// ---------------- layer-1 GEMM (F_IN=16, SIMT fp32) + logits ----------------
__global__ __launch_bounds__(128) void gemm_al_kernel(
    const float* __restrict__ x, const float* __restrict__ W,
    const float* __restrict__ aS, const float* __restrict__ aD)
{
    constexpr int KT = 16;
    __shared__ float Ws[KT][HID];
    __shared__ float xs[KT][32];
    __shared__ unsigned s_mx[Hh];
    float* __restrict__ hout = g_h0;

    int tid = threadIdx.x;
    int cx = tid & 31, ry = tid >> 5;
    int r0 = blockIdx.x * 32;
    float acc[8][4] = {};

    if (tid < Hh) s_mx[tid] = fkeyu(-1e30f);

    for (int kt = 0; kt < F_IN; kt += KT) {
#pragma unroll
        for (int k = 0; k < KT; k++) Ws[k][tid] = W[(kt + k) * HID + tid];
#pragma unroll
        for (int it = 0; it < 4; it++) {
            int lin = tid + it * 128;
            int r = lin >> 4, k = lin & 15;
            int row = r0 + r;
            xs[k][r] = (row < Nn) ? x[row * F_IN + kt + k] : 0.f;
        }
        __syncthreads();
#pragma unroll
        for (int k = 0; k < KT; k++) {
            float4 w4 = *(const float4*)&Ws[k][cx * 4];
#pragma unroll
            for (int r = 0; r < 8; r++) {
                float xv = xs[k][ry * 8 + r];
                acc[r][0] += xv * w4.x;
                acc[r][1] += xv * w4.y;
                acc[r][2] += xv * w4.z;
                acc[r][3] += xv * w4.w;
            }
        }
        __syncthreads();
    }

    int hd = cx >> 2;
    float a_s[4], a_d[4];
#pragma unroll
    for (int j = 0; j < 4; j++) {
        int c = (cx * 4 + j) & 15;
        a_s[j] = aS[hd * 16 + c];
        a_d[j] = aD[hd * 16 + c];
    }
    float locmax = -1e30f;
#pragma unroll
    for (int r = 0; r < 8; r++) {
        int row = r0 + ry * 8 + r;
        if (row >= Nn) break;
        float4 hv = make_float4(acc[r][0], acc[r][1], acc[r][2], acc[r][3]);
        *(float4*)&hout[row * HID + cx * 4] = hv;
        float ps = acc[r][0] * a_s[0] + acc[r][1] * a_s[1] + acc[r][2] * a_s[2] + acc[r][3] * a_s[3];
        float pd = acc[r][0] * a_d[0] + acc[r][1] * a_d[1] + acc[r][2] * a_d[2] + acc[r][3] * a_d[3];
        ps += __shfl_xor_sync(0xffffffffu, ps, 1);
        ps += __shfl_xor_sync(0xffffffffu, ps, 2);
        pd += __shfl_xor_sync(0xffffffffu, pd, 1);
        pd += __shfl_xor_sync(0xffffffffu, pd, 2);
        if ((cx & 3) == 0) {
            g_alS[row * Hh + hd] = ps;
            g_alD[row * Hh + hd] = pd;
            locmax = fmaxf(locmax, ps);
        }
    }
    if ((cx & 3) == 0) atomicMax(&s_mx[hd], fkeyu(locmax));
    __syncthreads();
    if (tid < Hh) atomicMax(&g_maxS[tid], s_mx[tid]);   // layer 0 slots
}

// ---------------- layers 2/3 GEMM (128x128, tf32 tensor cores) + logits ------
#define WS_STR 136
#define XS_STR 132
#define NTILES ((Nn + 63) / 64)   // 782
#define SMEM_TF (128 * WS_STR * 4 + 64 * XS_STR * 4 + 32)

__global__ __launch_bounds__(256, 2) void gemm_tf32_kernel(
    const float* __restrict__ W,
    const float* __restrict__ aS, const float* __restrict__ aD,
    int mslot)
{
    extern __shared__ float smem[];
    float* Ws = smem;                          // [128][WS_STR]
    float* xs = smem + 128 * WS_STR;           // [64][XS_STR]
    unsigned* s_mx = (unsigned*)(xs + 64 * XS_STR);

    int tid = threadIdx.x;
    int warp = tid >> 5, lane = tid & 31;
    int mw = warp >> 2, nw = warp & 3;
    int g = lane >> 2, t = lane & 3;

    for (int i = tid; i < 128 * 128; i += 256) {
        int k = i >> 7, n = i & 127;
        Ws[k * WS_STR + n] = tf32r(W[i]);
    }
    if (tid < Hh) s_mx[tid] = fkeyu(-1e30f);

    float asv0[4], asv1[4], adv0[4], adv1[4];
#pragma unroll
    for (int nt = 0; nt < 4; nt++) {
        int col = nw * 32 + nt * 8 + 2 * t;
        asv0[nt] = aS[col]; asv1[nt] = aS[col + 1];
        adv0[nt] = aD[col]; adv1[nt] = aD[col + 1];
    }
    __syncthreads();

    for (int tile = blockIdx.x; tile < NTILES; tile += gridDim.x) {
        int row0 = tile * 64;

        for (int i = tid; i < 64 * 32; i += 256) {
            int r = i >> 5, c4 = i & 31;
            int row = row0 + r;
            float4 v = make_float4(0.f, 0.f, 0.f, 0.f);
            if (row < Nn) v = *(const float4*)&g_h1[row * HID + c4 * 4];
            float* p = &xs[r * XS_STR + c4 * 4];
            p[0] = tf32r(v.x); p[1] = tf32r(v.y); p[2] = tf32r(v.z); p[3] = tf32r(v.w);
        }
        __syncthreads();

        float c[2][4][4];
#pragma unroll
        for (int mt = 0; mt < 2; mt++)
#pragma unroll
            for (int nt = 0; nt < 4; nt++)
#pragma unroll
                for (int q = 0; q < 4; q++) c[mt][nt][q] = 0.f;

#pragma unroll
        for (int ks = 0; ks < 16; ks++) {
            int k0 = ks * 8;
            float a[2][4], b[4][2];
#pragma unroll
            for (int mt = 0; mt < 2; mt++) {
                int r = mw * 32 + mt * 16 + g;
                a[mt][0] = xs[r * XS_STR + k0 + t];
                a[mt][1] = xs[(r + 8) * XS_STR + k0 + t];
                a[mt][2] = xs[r * XS_STR + k0 + t + 4];
                a[mt][3] = xs[(r + 8) * XS_STR + k0 + t + 4];
            }
#pragma unroll
            for (int nt = 0; nt < 4; nt++) {
                int n = nw * 32 + nt * 8 + g;
                b[nt][0] = Ws[(k0 + t) * WS_STR + n];
                b[nt][1] = Ws[(k0 + t + 4) * WS_STR + n];
            }
#pragma unroll
            for (int mt = 0; mt < 2; mt++)
#pragma unroll
                for (int nt = 0; nt < 4; nt++)
                    mma_tf32(c[mt][nt], a[mt], b[nt]);
        }

        float ps[2][2][2] = {}, pd[2][2][2] = {};   // [mt][half][headidx]
#pragma unroll
        for (int mt = 0; mt < 2; mt++) {
            int rlo = row0 + mw * 32 + mt * 16 + g;
            int rhi = rlo + 8;
#pragma unroll
            for (int nt = 0; nt < 4; nt++) {
                int col = nw * 32 + nt * 8 + 2 * t;
                float c0 = c[mt][nt][0], c1 = c[mt][nt][1];
                float c2 = c[mt][nt][2], c3 = c[mt][nt][3];
                if (rlo < Nn) { float2 v = make_float2(c0, c1); *(float2*)&g_h0[rlo * HID + col] = v; }
                if (rhi < Nn) { float2 v = make_float2(c2, c3); *(float2*)&g_h0[rhi * HID + col] = v; }
                int hi = nt >> 1;
                ps[mt][0][hi] += c0 * asv0[nt] + c1 * asv1[nt];
                ps[mt][1][hi] += c2 * asv0[nt] + c3 * asv1[nt];
                pd[mt][0][hi] += c0 * adv0[nt] + c1 * adv1[nt];
                pd[mt][1][hi] += c2 * adv0[nt] + c3 * adv1[nt];
            }
        }
#pragma unroll
        for (int mt = 0; mt < 2; mt++)
#pragma unroll
            for (int hf = 0; hf < 2; hf++)
#pragma unroll
                for (int hi = 0; hi < 2; hi++) {
                    float v = ps[mt][hf][hi];
                    v += __shfl_xor_sync(0xffffffffu, v, 1);
                    v += __shfl_xor_sync(0xffffffffu, v, 2);
                    ps[mt][hf][hi] = v;
                    float w = pd[mt][hf][hi];
                    w += __shfl_xor_sync(0xffffffffu, w, 1);
                    w += __shfl_xor_sync(0xffffffffu, w, 2);
                    pd[mt][hf][hi] = w;
                }
        if (t == 0) {
            float lm0 = -1e30f, lm1 = -1e30f;
#pragma unroll
            for (int mt = 0; mt < 2; mt++)
#pragma unroll
                for (int hf = 0; hf < 2; hf++) {
                    int row = row0 + mw * 32 + mt * 16 + hf * 8 + g;
                    if (row < Nn) {
                        int head = nw * 2;
                        g_alS[row * Hh + head]     = ps[mt][hf][0];
                        g_alD[row * Hh + head]     = pd[mt][hf][0];
                        g_alS[row * Hh + head + 1] = ps[mt][hf][1];
                        g_alD[row * Hh + head + 1] = pd[mt][hf][1];
                        lm0 = fmaxf(lm0, ps[mt][hf][0]);
                        lm1 = fmaxf(lm1, ps[mt][hf][1]);
                    }
                }
            atomicMax(&s_mx[nw * 2],     fkeyu(lm0));
            atomicMax(&s_mx[nw * 2 + 1], fkeyu(lm1));
        }
        __syncthreads();
    }
    if (tid < Hh) atomicMax(&g_maxS[mslot + tid], s_mx[tid]);
}

// ---------------- fused edge kernel (R9/R15 form): softmax + aggregate -------
// One warp per dst node, 4 warps/block; lane owns channels [4*lane,4*lane+4).
template <bool FC>
__global__ __launch_bounds__(128) void agg2_kernel(
    const float* __restrict__ bias,
    const float* __restrict__ fcw, const float* __restrict__ fcb,
    float* __restrict__ fco, int mslot)
{
    int warp = threadIdx.x >> 5, lane = threadIdx.x & 31;
    int d = blockIdx.x * 4 + warp;
    if (d >= Nn) return;
    int hd = lane >> 2;

    float alDh = g_alD[d * Hh + hd];
    float cb = fkeyinv(g_maxS[mslot + hd]) + alDh;
    cb = (cb > 0.f) ? cb : NEG_SLOPE * cb;

    int beg = g_rowptr[d], end = g_rowptr[d + 1];
    float4 acc = make_float4(0.f, 0.f, 0.f, 0.f);
    float den = 0.f;

    int cnt = min(32, end - beg);
    int s32 = (lane < cnt) ? g_csrsrc[beg + lane] : 0;

    for (int base = beg; base < end; ) {
        int nbase = base + 32;
        int ncnt = min(32, end - nbase);
        int ns32 = (nbase < end && lane < ncnt) ? g_csrsrc[nbase + lane] : 0;

        int jj = 0;
        for (; jj + 4 <= cnt; jj += 4) {
            int s0 = __shfl_sync(0xffffffffu, s32, jj);
            int s1 = __shfl_sync(0xffffffffu, s32, jj + 1);
            int s2 = __shfl_sync(0xffffffffu, s32, jj + 2);
            int s3 = __shfl_sync(0xffffffffu, s32, jj + 3);
            float l0 = g_alS[s0 * Hh + hd] + alDh;
            float l1 = g_alS[s1 * Hh + hd] + alDh;
            float l2 = g_alS[s2 * Hh + hd] + alDh;
            float l3 = g_alS[s3 * Hh + hd] + alDh;
            float4 h0 = *(const float4*)&g_h0[s0 * HID + lane * 4];
            float4 h1 = *(const float4*)&g_h0[s1 * HID + lane * 4];
            float4 h2 = *(const float4*)&g_h0[s2 * HID + lane * 4];
            float4 h3 = *(const float4*)&g_h0[s3 * HID + lane * 4];
            l0 = (l0 > 0.f) ? l0 : NEG_SLOPE * l0;
            l1 = (l1 > 0.f) ? l1 : NEG_SLOPE * l1;
            l2 = (l2 > 0.f) ? l2 : NEG_SLOPE * l2;
            l3 = (l3 > 0.f) ? l3 : NEG_SLOPE * l3;
            float p0 = __expf(l0 - cb);
            float p1 = __expf(l1 - cb);
            float p2 = __expf(l2 - cb);
            float p3 = __expf(l3 - cb);
            acc.x += p0 * h0.x + p1 * h1.x + p2 * h2.x + p3 * h3.x;
            acc.y += p0 * h0.y + p1 * h1.y + p2 * h2.y + p3 * h3.y;
            acc.z += p0 * h0.z + p1 * h1.z + p2 * h2.z + p3 * h3.z;
            acc.w += p0 * h0.w + p1 * h1.w + p2 * h2.w + p3 * h3.w;
            den += (p0 + p1) + (p2 + p3);
        }
        for (; jj < cnt; jj++) {
            int s0 = __shfl_sync(0xffffffffu, s32, jj);
            float l0 = g_alS[s0 * Hh + hd] + alDh;
            l0 = (l0 > 0.f) ? l0 : NEG_SLOPE * l0;
            float p0 = __expf(l0 - cb);
            float4 h0 = *(const float4*)&g_h0[s0 * HID + lane * 4];
            acc.x += p0 * h0.x;
            acc.y += p0 * h0.y;
            acc.z += p0 * h0.z;
            acc.w += p0 * h0.w;
            den += p0;
        }

        base = nbase;
        cnt = ncnt;
        s32 = ns32;
    }

    float inv = 1.f / den;
    float4 b4 = *(const float4*)&bias[lane * 4];
    float4 o;
    o.x = acc.x * inv + b4.x;
    o.y = acc.y * inv + b4.y;
    o.z = acc.z * inv + b4.z;
    o.w = acc.w * inv + b4.w;
    o.x = (o.x > 0.f) ? o.x : (__expf(o.x) - 1.f);
    o.y = (o.y > 0.f) ? o.y : (__expf(o.y) - 1.f);
    o.z = (o.z > 0.f) ? o.z : (__expf(o.z) - 1.f);
    o.w = (o.w > 0.f) ? o.w : (__expf(o.w) - 1.f);

    if (!FC) {
        *(float4*)&g_h1[d * HID + lane * 4] = o;
    } else {
        float4 fw = *(const float4*)&fcw[lane * 4];
        float v = o.x * fw.x + o.y * fw.y + o.z * fw.z + o.w * fw.w;
#pragma unroll
        for (int off = 16; off; off >>= 1) v += __shfl_xor_sync(0xffffffffu, v, off);
        if (lane == 0) fco[d] = v + fcb[0];
    }
}

// ---------------- launch ----------------
extern "C" void kernel_launch(void* const* d_in, const int* in_sizes, int n_in,
                              void* d_out, int out_size)
{
    const float* x   = (const float*)d_in[0];
    const int*   ei  = (const int*)d_in[1];   // int32 (JAX default downcast)
    const float* W1  = (const float*)d_in[2];
    const float* a1s = (const float*)d_in[3];
    const float* a1d = (const float*)d_in[4];
    const float* b1  = (const float*)d_in[5];
    const float* W2  = (const float*)d_in[6];
    const float* a2s = (const float*)d_in[7];
    const float* a2d = (const float*)d_in[8];
    const float* b2  = (const float*)d_in[9];
    const float* W3  = (const float*)d_in[10];
    const float* a3s = (const float*)d_in[11];
    const float* a3d = (const float*)d_in[12];
    const float* b3  = (const float*)d_in[13];
    const float* fcw = (const float*)d_in[14];
    const float* fcb = (const float*)d_in[15];
    float* out = (float*)d_out;

    cudaFuncSetAttribute(gemm_tf32_kernel,
                         cudaFuncAttributeMaxDynamicSharedMemorySize, SMEM_TF);

    // CSR build: 4 kernels, hist/scatter vectorized 4 edges/thread.
    const int ev_blocks = ((ET + 3) / 4 + 255) / 256;
    k_hist<<<ev_blocks, 256>>>(ei);
    k_scan_a<<<NB, SB>>>();
    k_scan_c<<<NB, SB>>>();
    k_scatter<<<ev_blocks, 256>>>(ei);

    const int gemm1_blocks = (Nn + 31) / 32;
    const int agg_blocks   = (Nn + 3) / 4;

    // layer 1 (SIMT fp32, maxS slots 0..7)
    gemm_al_kernel<<<gemm1_blocks, 128>>>(x, W1, a1s, a1d);
    agg2_kernel<false><<<agg_blocks, 128>>>(b1, nullptr, nullptr, nullptr, 0);

    // layer 2 (tf32 tensor cores, maxS slots 8..15)
    gemm_tf32_kernel<<<296, 256, SMEM_TF>>>(W2, a2s, a2d, 8);
    agg2_kernel<false><<<agg_blocks, 128>>>(b2, nullptr, nullptr, nullptr, 8);

    // layer 3 (tf32 tensor cores, maxS slots 16..23, + fused fc head)
    gemm_tf32_kernel<<<296, 256, SMEM_TF>>>(W3, a3s, a3d, 16);
    agg2_kernel<true><<<agg_blocks, 128>>>(b3, fcw, fcb, out, 16);
}